// round 6
// baseline (speedup 1.0000x reference)
#include <cuda_runtime.h>
#include <cuda_bf16.h>
#include <math.h>
#include <stdint.h>

#define BATCH   16384
#define IN_DIM  1024
#define NODES   1023
#define NODES_PAD 1024
#define LEAVES  1024
#define OUT_DIM 128
#define TREE_DEPTH 10

// ---------------------------------------------------------------------------
// Scratch
// ---------------------------------------------------------------------------
__device__ __nv_bfloat16 g_xs[2][BATCH][IN_DIM];      // hi/lo split of x  (64 MB)
__device__ __nv_bfloat16 g_ws[2][NODES_PAD][IN_DIM];  // hi/lo split of W  (4 MB)
__device__ float g_dec[(size_t)BATCH * NODES_PAD];    // 64 MB decisions
__device__ __nv_bfloat16 g_ps[2][BATCH][LEAVES];      // hi/lo split of leaf probs (64 MB)
__device__ __nv_bfloat16 g_lvs[2][OUT_DIM][LEAVES];   // hi/lo split of leaf_values^T (0.5 MB)
__device__ int   g_anymiss[BATCH];

__device__ __forceinline__ uint32_t smem_u32(const void* p) {
    uint32_t a;
    asm("{ .reg .u64 t; cvta.to.shared.u64 t, %1; cvt.u32.u64 %0, t; }" : "=r"(a) : "l"(p));
    return a;
}

// ---------------------------------------------------------------------------
// Converters
// ---------------------------------------------------------------------------
__global__ __launch_bounds__(256) void k_convert_x(const float* __restrict__ x) {
    size_t idx = (size_t)blockIdx.x * blockDim.x + threadIdx.x;   // float4 index
    if (idx * 4 >= (size_t)BATCH * IN_DIM) return;
    float4 v = ((const float4*)x)[idx];
    bool miss = (v.x != v.x) || (v.y != v.y) || (v.z != v.z) || (v.w != v.w);
    if (miss) atomicExch(&g_anymiss[(int)((idx * 4) / IN_DIM)], 1);
    float f[4] = { (v.x == v.x) ? v.x : 0.f, (v.y == v.y) ? v.y : 0.f,
                   (v.z == v.z) ? v.z : 0.f, (v.w == v.w) ? v.w : 0.f };
    __nv_bfloat16 hi[4], lo[4];
#pragma unroll
    for (int i = 0; i < 4; i++) {
        hi[i] = __float2bfloat16(f[i]);
        lo[i] = __float2bfloat16(f[i] - __bfloat162float(hi[i]));
    }
    *(uint2*)(&g_xs[0][0][0] + idx * 4) = *(uint2*)hi;
    *(uint2*)(&g_xs[1][0][0] + idx * 4) = *(uint2*)lo;
}

__global__ __launch_bounds__(256) void k_convert_w(const float* __restrict__ w) {
    size_t idx = (size_t)blockIdx.x * blockDim.x + threadIdx.x;
    if (idx * 4 >= (size_t)NODES_PAD * IN_DIM) return;
    size_t e = idx * 4;
    int n = (int)(e >> 10);
    float f[4] = {0.f, 0.f, 0.f, 0.f};
    if (n < NODES) { float4 v = *(const float4*)&w[e]; f[0] = v.x; f[1] = v.y; f[2] = v.z; f[3] = v.w; }
    __nv_bfloat16 hi[4], lo[4];
#pragma unroll
    for (int i = 0; i < 4; i++) {
        hi[i] = __float2bfloat16(f[i]);
        lo[i] = __float2bfloat16(f[i] - __bfloat162float(hi[i]));
    }
    *(uint2*)(&g_ws[0][0][0] + e) = *(uint2*)hi;
    *(uint2*)(&g_ws[1][0][0] + e) = *(uint2*)lo;
}

// leaf_values [k][n] fp32 -> transposed hi/lo bf16 [n][k]
__global__ __launch_bounds__(256) void k_convert_lv(const float* __restrict__ lv) {
    int idx = blockIdx.x * blockDim.x + threadIdx.x;
    if (idx >= LEAVES * OUT_DIM) return;
    int k = idx >> 7;
    int n = idx & 127;
    float f = lv[idx];
    __nv_bfloat16 hi = __float2bfloat16(f);
    __nv_bfloat16 lo = __float2bfloat16(f - __bfloat162float(hi));
    g_lvs[0][n][k] = hi;
    g_lvs[1][n][k] = lo;
}

// ---------------------------------------------------------------------------
// mma.sync machinery. CTA tile 128x128, BK=32, 3-stage cp.async pipeline.
// Each stage packs hi|lo side by side in 128B rows:
//   A row: [Ah k0..31 (64B) | Al k0..31 (64B)]   (128 rows, 16 KB)
//   B row: [Bh (64B) | Bl (64B)]                 (128 rows, 16 KB)
// All 3 hi/lo passes execute from one resident stage: 48 MMA / 12 ldsm per
// warp per k16 slice.
// ---------------------------------------------------------------------------
#define NSTAGES 3
#define BK 32
#define TOT_ITERS (IN_DIM / BK)            // 32
#define AB_TILE_B (128 * 128)              // 16384 (A-combined or B-combined)
#define STAGE_B  (2 * AB_TILE_B)           // 32768
#define GMM_SMEM (NSTAGES * STAGE_B)       // 98304

// swizzled offset for (row, 16B-chunk) in a 128-row x 128B tile (8-way XOR)
__device__ __forceinline__ uint32_t swz(uint32_t base, int row, int chunk) {
    return base + row * 128 + ((chunk ^ (row & 7)) << 4);
}

__device__ __forceinline__ void cp16(uint32_t saddr, const void* gaddr) {
    asm volatile("cp.async.cg.shared.global [%0], [%1], 16;" :: "r"(saddr), "l"(gaddr));
}

__device__ __forceinline__ void ldsm_x4(uint32_t addr, uint32_t& r0, uint32_t& r1,
                                        uint32_t& r2, uint32_t& r3) {
    asm volatile("ldmatrix.sync.aligned.m8n8.x4.shared.b16 {%0,%1,%2,%3}, [%4];"
                 : "=r"(r0), "=r"(r1), "=r"(r2), "=r"(r3) : "r"(addr));
}

__device__ __forceinline__ void mma16816(float* d, const uint32_t* a, const uint32_t* b) {
    asm volatile(
        "mma.sync.aligned.m16n8k16.row.col.f32.bf16.bf16.f32 "
        "{%0,%1,%2,%3}, {%4,%5,%6,%7}, {%8,%9}, {%0,%1,%2,%3};"
        : "+f"(d[0]), "+f"(d[1]), "+f"(d[2]), "+f"(d[3])
        : "r"(a[0]), "r"(a[1]), "r"(a[2]), "r"(a[3]), "r"(b[0]), "r"(b[1]));
}

// issue one BK=32 stage: hi|lo packed rows. 8 cp16 per thread (256 threads).
__device__ __forceinline__ void issue_stage(
    uint32_t sA,
    const __nv_bfloat16* __restrict__ Ah, const __nv_bfloat16* __restrict__ Al,
    const __nv_bfloat16* __restrict__ Bh, const __nv_bfloat16* __restrict__ Bl,
    int it, int m0, int n0, int t)
{
    const int kb  = it * BK;
    const int row = t >> 1;
    const int c0  = (t & 1) * 4;           // chunks c0..c0+3 (covers hi 0-3 or lo 4-7)
    const uint32_t sB = sA + AB_TILE_B;
#pragma unroll
    for (int j = 0; j < 4; j++) {
        int c = c0 + j;
        const __nv_bfloat16* As = (c < 4) ? Ah : Al;
        const __nv_bfloat16* Bs = (c < 4) ? Bh : Bl;
        int kc = (c & 3) * 8;
        cp16(swz(sA, row, c), As + (size_t)(m0 + row) * 1024 + kb + kc);
        cp16(swz(sB, row, c), Bs + (size_t)(n0 + row) * 1024 + kb + kc);
    }
    asm volatile("cp.async.commit_group;" ::: "memory");
}

// mainloop: all 3 passes per resident stage, accumulate into acc[2][8][4]
__device__ __forceinline__ void gemm_mainloop(
    float acc[2][8][4], uint32_t sb,
    const __nv_bfloat16* __restrict__ Ah, const __nv_bfloat16* __restrict__ Al,
    const __nv_bfloat16* __restrict__ Bh, const __nv_bfloat16* __restrict__ Bl,
    int m0, int n0, int t)
{
    const int warp = t >> 5;
    const int lane = t & 31;
    const int wm   = warp & 3;
    const int wn   = warp >> 2;
    const int a_r16 = lane & 15;
    const int lsub  = lane >> 4;
    const int b_row = ((lane >> 3) & 1) * 8 + (lane & 7);

#pragma unroll
    for (int i = 0; i < NSTAGES - 1; i++)
        issue_stage(sb + i * STAGE_B, Ah, Al, Bh, Bl, i, m0, n0, t);

    for (int it = 0; it < TOT_ITERS; it++) {
        asm volatile("cp.async.wait_group %0;" :: "n"(NSTAGES - 2) : "memory");
        __syncthreads();

        if (it + NSTAGES - 1 < TOT_ITERS) {
            int is = it + NSTAGES - 1;
            issue_stage(sb + (is % NSTAGES) * STAGE_B, Ah, Al, Bh, Bl, is, m0, n0, t);
        } else {
            asm volatile("cp.async.commit_group;" ::: "memory");
        }

        const uint32_t sA = sb + (it % NSTAGES) * STAGE_B;
        const uint32_t sB = sA + AB_TILE_B;

#pragma unroll
        for (int h = 0; h < 2; h++) {          // two k16 slices of BK=32
            const int chH = h * 2 + lsub;      // hi chunks 0..3
            const int chL = 4 + chH;           // lo chunks 4..7

            // --- load A_hi, B_hi; pass hi*hi ---
            uint32_t ah[2][4];
#pragma unroll
            for (int mf = 0; mf < 2; mf++) {
                int row = wm * 32 + mf * 16 + a_r16;
                ldsm_x4(swz(sA, row, chH), ah[mf][0], ah[mf][1], ah[mf][2], ah[mf][3]);
            }
            uint32_t bh[8][2];
#pragma unroll
            for (int nb = 0; nb < 4; nb++) {
                int row = wn * 64 + nb * 16 + b_row;
                ldsm_x4(swz(sB, row, chH),
                        bh[2 * nb][0], bh[2 * nb + 1][0], bh[2 * nb][1], bh[2 * nb + 1][1]);
            }
#pragma unroll
            for (int mf = 0; mf < 2; mf++)
#pragma unroll
                for (int nf = 0; nf < 8; nf++)
                    mma16816(acc[mf][nf], ah[mf], bh[nf]);

            // --- load A_lo; pass lo*hi (reuses B_hi) ---
            {
                uint32_t al[2][4];
#pragma unroll
                for (int mf = 0; mf < 2; mf++) {
                    int row = wm * 32 + mf * 16 + a_r16;
                    ldsm_x4(swz(sA, row, chL), al[mf][0], al[mf][1], al[mf][2], al[mf][3]);
                }
#pragma unroll
                for (int mf = 0; mf < 2; mf++)
#pragma unroll
                    for (int nf = 0; nf < 8; nf++)
                        mma16816(acc[mf][nf], al[mf], bh[nf]);
            }

            // --- load B_lo; pass hi*lo (reuses A_hi) ---
            {
                uint32_t bl[8][2];
#pragma unroll
                for (int nb = 0; nb < 4; nb++) {
                    int row = wn * 64 + nb * 16 + b_row;
                    ldsm_x4(swz(sB, row, chL),
                            bl[2 * nb][0], bl[2 * nb + 1][0], bl[2 * nb][1], bl[2 * nb + 1][1]);
                }
#pragma unroll
                for (int mf = 0; mf < 2; mf++)
#pragma unroll
                    for (int nf = 0; nf < 8; nf++)
                        mma16816(acc[mf][nf], ah[mf], bl[nf]);
            }
        }
    }
}

// ---------------------------------------------------------------------------
// GEMM1: logits = x @ W^T + bias -> sigmoid -> g_dec
// ---------------------------------------------------------------------------
__global__ __launch_bounds__(256, 2)
void k_gemm1_mma(const float* __restrict__ bias, const float* __restrict__ temp)
{
    extern __shared__ char smem[];
    const uint32_t sb = smem_u32(smem);
    const int t    = threadIdx.x;
    const int warp = t >> 5;
    const int lane = t & 31;
    const int wm   = warp & 3;
    const int wn   = warp >> 2;
    const int m0   = blockIdx.y * 128;
    const int n0   = blockIdx.x * 128;

    float acc[2][8][4];
#pragma unroll
    for (int i = 0; i < 2; i++)
#pragma unroll
        for (int j = 0; j < 8; j++)
#pragma unroll
            for (int q = 0; q < 4; q++) acc[i][j][q] = 0.0f;

    gemm_mainloop(acc, sb, &g_xs[0][0][0], &g_xs[1][0][0],
                  &g_ws[0][0][0], &g_ws[1][0][0], m0, n0, t);

    const float invT = 1.0f / __ldg(temp);
    const int lr = lane >> 2;
    const int lc = (lane & 3) * 2;

#pragma unroll
    for (int mf = 0; mf < 2; mf++) {
        const int r0 = m0 + wm * 32 + mf * 16 + lr;
        const int r1 = r0 + 8;
        const int miss0 = g_anymiss[r0];
        const int miss1 = g_anymiss[r1];
        float* __restrict__ p0 = g_dec + (size_t)r0 * NODES_PAD;
        float* __restrict__ p1 = g_dec + (size_t)r1 * NODES_PAD;
#pragma unroll
        for (int nf = 0; nf < 8; nf++) {
            const int n = n0 + wn * 64 + nf * 8 + lc;
            const float bz0 = (n     < NODES) ? __ldg(&bias[n])     : 0.0f;
            const float bz1 = (n + 1 < NODES) ? __ldg(&bias[n + 1]) : 0.0f;
            const float* a4 = acc[mf][nf];
            float2 v0, v1;
            v0.x = miss0 ? 0.5f : 1.0f / (1.0f + __expf(-(a4[0] + bz0) * invT));
            v0.y = miss0 ? 0.5f : 1.0f / (1.0f + __expf(-(a4[1] + bz1) * invT));
            v1.x = miss1 ? 0.5f : 1.0f / (1.0f + __expf(-(a4[2] + bz0) * invT));
            v1.y = miss1 ? 0.5f : 1.0f / (1.0f + __expf(-(a4[3] + bz1) * invT));
            *(float2*)(p0 + n) = v0;
            *(float2*)(p1 + n) = v1;
        }
    }
}

// ---------------------------------------------------------------------------
// GEMM2: out = leaf_probs @ leaf_values (B = lv^T, n-major)
// ---------------------------------------------------------------------------
__global__ __launch_bounds__(256, 2)
void k_gemm2_mma(float* __restrict__ out)
{
    extern __shared__ char smem[];
    const uint32_t sb = smem_u32(smem);
    const int t    = threadIdx.x;
    const int warp = t >> 5;
    const int lane = t & 31;
    const int wm   = warp & 3;
    const int wn   = warp >> 2;
    const int m0   = blockIdx.x * 128;

    float acc[2][8][4];
#pragma unroll
    for (int i = 0; i < 2; i++)
#pragma unroll
        for (int j = 0; j < 8; j++)
#pragma unroll
            for (int q = 0; q < 4; q++) acc[i][j][q] = 0.0f;

    gemm_mainloop(acc, sb, &g_ps[0][0][0], &g_ps[1][0][0],
                  &g_lvs[0][0][0], &g_lvs[1][0][0], m0, 0, t);

    const int lr = lane >> 2;
    const int lc = (lane & 3) * 2;
#pragma unroll
    for (int mf = 0; mf < 2; mf++) {
        const int r0 = m0 + wm * 32 + mf * 16 + lr;
        const int r1 = r0 + 8;
        float* __restrict__ p0 = out + (size_t)r0 * OUT_DIM;
        float* __restrict__ p1 = out + (size_t)r1 * OUT_DIM;
#pragma unroll
        for (int nf = 0; nf < 8; nf++) {
            const int n = wn * 64 + nf * 8 + lc;
            const float* a4 = acc[mf][nf];
            *(float2*)(p0 + n) = make_float2(a4[0], a4[1]);
            *(float2*)(p1 + n) = make_float2(a4[2], a4[3]);
        }
    }
}

// ---------------------------------------------------------------------------
// Routing kernel: emits probs as bf16 hi/lo split
// ---------------------------------------------------------------------------
__global__ __launch_bounds__(128) void k_route() {
    __shared__ float buf[2][LEAVES];
    const int row = blockIdx.x;
    const int tid = threadIdx.x;
    const float* __restrict__ drow = g_dec + (size_t)row * NODES_PAD;

    if (tid == 0) buf[0][0] = 1.0f;
    __syncthreads();

    int cur = 0;
#pragma unroll
    for (int L = 0; L < TREE_DEPTH; L++) {
        int n = 1 << L;
        for (int i = tid; i < n; i += 128) {
            float dd = drow[n - 1 + i];
            float v  = buf[cur][i];
            buf[cur ^ 1][i]     = v * dd;
            buf[cur ^ 1][n + i] = v * (1.0f - dd);
        }
        __syncthreads();
        cur ^= 1;
    }

    __nv_bfloat16* __restrict__ ph = &g_ps[0][row][0];
    __nv_bfloat16* __restrict__ pl = &g_ps[1][row][0];
    for (int i = tid; i < LEAVES; i += 128) {
        float p = buf[cur][i];
        __nv_bfloat16 h = __float2bfloat16(p);
        __nv_bfloat16 l = __float2bfloat16(p - __bfloat162float(h));
        ph[i] = h;
        pl[i] = l;
    }
}

// ---------------------------------------------------------------------------
// Launch
// ---------------------------------------------------------------------------
extern "C" void kernel_launch(void* const* d_in, const int* in_sizes, int n_in,
                              void* d_out, int out_size)
{
    const float* x    = (const float*)d_in[0];
    const float* w    = (const float*)d_in[1];
    const float* bias = (const float*)d_in[2];
    const float* lv   = (const float*)d_in[3];
    const float* temp = (const float*)d_in[4];
    float* out = (float*)d_out;

    static int smem_set = 0;
    if (!smem_set) {
        cudaFuncSetAttribute(k_gemm1_mma, cudaFuncAttributeMaxDynamicSharedMemorySize, GMM_SMEM);
        cudaFuncSetAttribute(k_gemm2_mma, cudaFuncAttributeMaxDynamicSharedMemorySize, GMM_SMEM);
        smem_set = 1;
    }

    {
        size_t n4 = (size_t)BATCH * IN_DIM / 4;
        k_convert_x<<<(unsigned)((n4 + 255) / 256), 256>>>(x);
    }
    {
        size_t n4 = (size_t)NODES_PAD * IN_DIM / 4;
        k_convert_w<<<(unsigned)((n4 + 255) / 256), 256>>>(w);
    }
    k_convert_lv<<<(LEAVES * OUT_DIM + 255) / 256, 256>>>(lv);
    {
        dim3 grid(NODES_PAD / 128, BATCH / 128);   // (8, 128)
        k_gemm1_mma<<<grid, 256, GMM_SMEM>>>(bias, temp);
    }
    k_route<<<BATCH, 128>>>();
    k_gemm2_mma<<<BATCH / 128, 256, GMM_SMEM>>>(out);
}

// round 7
// speedup vs baseline: 1.3225x; 1.3225x over previous
#include <cuda_runtime.h>
#include <cuda_bf16.h>
#include <math.h>
#include <stdint.h>

#define BATCH   16384
#define IN_DIM  1024
#define NODES   1023
#define NODES_PAD 1024
#define LEAVES  1024
#define OUT_DIM 128
#define TREE_DEPTH 10

// ---------------------------------------------------------------------------
// Scratch
// ---------------------------------------------------------------------------
__device__ __nv_bfloat16 g_xs[2][BATCH][IN_DIM];      // hi/lo split of x  (64 MB)
__device__ __nv_bfloat16 g_ws[2][NODES_PAD][IN_DIM];  // hi/lo split of W  (4 MB)
__device__ float g_dec[(size_t)BATCH * NODES_PAD];    // 64 MB decisions
__device__ __nv_bfloat16 g_ps[2][BATCH][LEAVES];      // hi/lo split of leaf probs (64 MB)
__device__ __nv_bfloat16 g_lvs[2][OUT_DIM][LEAVES];   // hi/lo split of leaf_values^T (0.5 MB)
__device__ int   g_anymiss[BATCH];

__device__ __forceinline__ uint32_t smem_u32(const void* p) {
    uint32_t a;
    asm("{ .reg .u64 t; cvta.to.shared.u64 t, %1; cvt.u32.u64 %0, t; }" : "=r"(a) : "l"(p));
    return a;
}

// ---------------------------------------------------------------------------
// Converters
// ---------------------------------------------------------------------------
__global__ __launch_bounds__(256) void k_convert_x(const float* __restrict__ x) {
    size_t idx = (size_t)blockIdx.x * blockDim.x + threadIdx.x;   // float4 index
    if (idx * 4 >= (size_t)BATCH * IN_DIM) return;
    float4 v = ((const float4*)x)[idx];
    bool miss = (v.x != v.x) || (v.y != v.y) || (v.z != v.z) || (v.w != v.w);
    if (miss) atomicExch(&g_anymiss[(int)((idx * 4) / IN_DIM)], 1);
    float f[4] = { (v.x == v.x) ? v.x : 0.f, (v.y == v.y) ? v.y : 0.f,
                   (v.z == v.z) ? v.z : 0.f, (v.w == v.w) ? v.w : 0.f };
    __nv_bfloat16 hi[4], lo[4];
#pragma unroll
    for (int i = 0; i < 4; i++) {
        hi[i] = __float2bfloat16(f[i]);
        lo[i] = __float2bfloat16(f[i] - __bfloat162float(hi[i]));
    }
    *(uint2*)(&g_xs[0][0][0] + idx * 4) = *(uint2*)hi;
    *(uint2*)(&g_xs[1][0][0] + idx * 4) = *(uint2*)lo;
}

__global__ __launch_bounds__(256) void k_convert_w(const float* __restrict__ w) {
    size_t idx = (size_t)blockIdx.x * blockDim.x + threadIdx.x;
    if (idx * 4 >= (size_t)NODES_PAD * IN_DIM) return;
    size_t e = idx * 4;
    int n = (int)(e >> 10);
    float f[4] = {0.f, 0.f, 0.f, 0.f};
    if (n < NODES) { float4 v = *(const float4*)&w[e]; f[0] = v.x; f[1] = v.y; f[2] = v.z; f[3] = v.w; }
    __nv_bfloat16 hi[4], lo[4];
#pragma unroll
    for (int i = 0; i < 4; i++) {
        hi[i] = __float2bfloat16(f[i]);
        lo[i] = __float2bfloat16(f[i] - __bfloat162float(hi[i]));
    }
    *(uint2*)(&g_ws[0][0][0] + e) = *(uint2*)hi;
    *(uint2*)(&g_ws[1][0][0] + e) = *(uint2*)lo;
}

// leaf_values [k][n] fp32 -> transposed hi/lo bf16 [n][k]
__global__ __launch_bounds__(256) void k_convert_lv(const float* __restrict__ lv) {
    int idx = blockIdx.x * blockDim.x + threadIdx.x;
    if (idx >= LEAVES * OUT_DIM) return;
    int k = idx >> 7;
    int n = idx & 127;
    float f = lv[idx];
    __nv_bfloat16 hi = __float2bfloat16(f);
    __nv_bfloat16 lo = __float2bfloat16(f - __bfloat162float(hi));
    g_lvs[0][n][k] = hi;
    g_lvs[1][n][k] = lo;
}

// ---------------------------------------------------------------------------
// mma.sync machinery. CTA tile 128x128, 512 threads, 16 warps (4M x 4N),
// warp tile 32x32 (acc = 32 regs/thread -> 2 CTAs/SM, 32 warps/SM).
// BK=64, 3-stage cp.async pipeline, serialized 3-pass hi/lo (K_eff = 3*1024).
// ---------------------------------------------------------------------------
#define NSTAGES 3
#define BK 64
#define TOT_ITERS 48                       // 3 segs * 16
#define AB_TILE_B (128 * 128)              // 128 rows * 64 bf16 = 16384 B
#define STAGE_B  (2 * AB_TILE_B)           // 32768
#define GMM_SMEM (NSTAGES * STAGE_B)       // 98304

// swizzled offset for (row, 16B-chunk) in a 128-row x 128B tile (8-way XOR)
__device__ __forceinline__ uint32_t swz(uint32_t base, int row, int chunk) {
    return base + row * 128 + ((chunk ^ (row & 7)) << 4);
}

__device__ __forceinline__ void cp16(uint32_t saddr, const void* gaddr) {
    asm volatile("cp.async.cg.shared.global [%0], [%1], 16;" :: "r"(saddr), "l"(gaddr));
}

__device__ __forceinline__ void ldsm_x4(uint32_t addr, uint32_t& r0, uint32_t& r1,
                                        uint32_t& r2, uint32_t& r3) {
    asm volatile("ldmatrix.sync.aligned.m8n8.x4.shared.b16 {%0,%1,%2,%3}, [%4];"
                 : "=r"(r0), "=r"(r1), "=r"(r2), "=r"(r3) : "r"(addr));
}

__device__ __forceinline__ void mma16816(float* d, const uint32_t* a, const uint32_t* b) {
    asm volatile(
        "mma.sync.aligned.m16n8k16.row.col.f32.bf16.bf16.f32 "
        "{%0,%1,%2,%3}, {%4,%5,%6,%7}, {%8,%9}, {%0,%1,%2,%3};"
        : "+f"(d[0]), "+f"(d[1]), "+f"(d[2]), "+f"(d[3])
        : "r"(a[0]), "r"(a[1]), "r"(a[2]), "r"(a[3]), "r"(b[0]), "r"(b[1]));
}

// issue one BK=64 stage: 4 cp16 per thread (512 threads), plain seg layout
__device__ __forceinline__ void issue_stage(
    uint32_t sA,
    const __nv_bfloat16* __restrict__ Ah, const __nv_bfloat16* __restrict__ Al,
    const __nv_bfloat16* __restrict__ Bh, const __nv_bfloat16* __restrict__ Bl,
    int it, int m0, int n0, int t)
{
    const int seg = it >> 4;               // 0,1,2
    const int kb  = (it & 15) * BK;
    const __nv_bfloat16* Asrc = (seg < 2) ? Ah : Al;   // hi, hi, lo
    const __nv_bfloat16* Bsrc = (seg == 1) ? Bl : Bh;  // hi, lo, hi
    const int row = t >> 2;                // 0..127
    const int c0  = (t & 3) * 2;           // 0,2,4,6
    const uint32_t sB = sA + AB_TILE_B;
#pragma unroll
    for (int j = 0; j < 2; j++) {
        int c = c0 + j;
        cp16(swz(sA, row, c), Asrc + (size_t)(m0 + row) * 1024 + kb + c * 8);
        cp16(swz(sB, row, c), Bsrc + (size_t)(n0 + row) * 1024 + kb + c * 8);
    }
    asm volatile("cp.async.commit_group;" ::: "memory");
}

// mainloop: accumulates 3-pass product into acc[2][4][4]
__device__ __forceinline__ void gemm_mainloop(
    float acc[2][4][4], uint32_t sb,
    const __nv_bfloat16* __restrict__ Ah, const __nv_bfloat16* __restrict__ Al,
    const __nv_bfloat16* __restrict__ Bh, const __nv_bfloat16* __restrict__ Bl,
    int m0, int n0, int t)
{
    const int warp = t >> 5;
    const int lane = t & 31;
    const int wm   = warp & 3;             // 0..3 (M, 32 rows)
    const int wn   = warp >> 2;            // 0..3 (N, 32 cols)
    const int a_r16 = lane & 15;
    const int lsub  = lane >> 4;
    const int b_row = ((lane >> 3) & 1) * 8 + (lane & 7);

#pragma unroll
    for (int i = 0; i < NSTAGES - 1; i++)
        issue_stage(sb + i * STAGE_B, Ah, Al, Bh, Bl, i, m0, n0, t);

    for (int it = 0; it < TOT_ITERS; it++) {
        asm volatile("cp.async.wait_group %0;" :: "n"(NSTAGES - 2) : "memory");
        __syncthreads();

        if (it + NSTAGES - 1 < TOT_ITERS) {
            int is = it + NSTAGES - 1;
            issue_stage(sb + (is % NSTAGES) * STAGE_B, Ah, Al, Bh, Bl, is, m0, n0, t);
        } else {
            asm volatile("cp.async.commit_group;" ::: "memory");
        }

        const uint32_t sA = sb + (it % NSTAGES) * STAGE_B;
        const uint32_t sB = sA + AB_TILE_B;

#pragma unroll
        for (int h = 0; h < 4; h++) {          // four k16 slices of BK=64
            const int ch = h * 2 + lsub;
            uint32_t a[2][4];
#pragma unroll
            for (int mf = 0; mf < 2; mf++) {
                int row = wm * 32 + mf * 16 + a_r16;
                ldsm_x4(swz(sA, row, ch), a[mf][0], a[mf][1], a[mf][2], a[mf][3]);
            }
            uint32_t b[4][2];
#pragma unroll
            for (int nb = 0; nb < 2; nb++) {
                int row = wn * 32 + nb * 16 + b_row;
                ldsm_x4(swz(sB, row, ch),
                        b[2 * nb][0], b[2 * nb + 1][0], b[2 * nb][1], b[2 * nb + 1][1]);
            }
#pragma unroll
            for (int mf = 0; mf < 2; mf++)
#pragma unroll
                for (int nf = 0; nf < 4; nf++)
                    mma16816(acc[mf][nf], a[mf], b[nf]);
        }
    }
}

// ---------------------------------------------------------------------------
// GEMM1: logits = x @ W^T + bias -> sigmoid -> g_dec
// ---------------------------------------------------------------------------
__global__ __launch_bounds__(512, 2)
void k_gemm1_mma(const float* __restrict__ bias, const float* __restrict__ temp)
{
    extern __shared__ char smem[];
    const uint32_t sb = smem_u32(smem);
    const int t    = threadIdx.x;
    const int warp = t >> 5;
    const int lane = t & 31;
    const int wm   = warp & 3;
    const int wn   = warp >> 2;
    const int m0   = blockIdx.y * 128;
    const int n0   = blockIdx.x * 128;

    float acc[2][4][4];
#pragma unroll
    for (int i = 0; i < 2; i++)
#pragma unroll
        for (int j = 0; j < 4; j++)
#pragma unroll
            for (int q = 0; q < 4; q++) acc[i][j][q] = 0.0f;

    gemm_mainloop(acc, sb, &g_xs[0][0][0], &g_xs[1][0][0],
                  &g_ws[0][0][0], &g_ws[1][0][0], m0, n0, t);

    const float invT = 1.0f / __ldg(temp);
    const int lr = lane >> 2;
    const int lc = (lane & 3) * 2;

#pragma unroll
    for (int mf = 0; mf < 2; mf++) {
        const int r0 = m0 + wm * 32 + mf * 16 + lr;
        const int r1 = r0 + 8;
        const int miss0 = g_anymiss[r0];
        const int miss1 = g_anymiss[r1];
        float* __restrict__ p0 = g_dec + (size_t)r0 * NODES_PAD;
        float* __restrict__ p1 = g_dec + (size_t)r1 * NODES_PAD;
#pragma unroll
        for (int nf = 0; nf < 4; nf++) {
            const int n = n0 + wn * 32 + nf * 8 + lc;
            const float bz0 = (n     < NODES) ? __ldg(&bias[n])     : 0.0f;
            const float bz1 = (n + 1 < NODES) ? __ldg(&bias[n + 1]) : 0.0f;
            const float* a4 = acc[mf][nf];
            float2 v0, v1;
            v0.x = miss0 ? 0.5f : 1.0f / (1.0f + __expf(-(a4[0] + bz0) * invT));
            v0.y = miss0 ? 0.5f : 1.0f / (1.0f + __expf(-(a4[1] + bz1) * invT));
            v1.x = miss1 ? 0.5f : 1.0f / (1.0f + __expf(-(a4[2] + bz0) * invT));
            v1.y = miss1 ? 0.5f : 1.0f / (1.0f + __expf(-(a4[3] + bz1) * invT));
            *(float2*)(p0 + n) = v0;
            *(float2*)(p1 + n) = v1;
        }
    }
}

// ---------------------------------------------------------------------------
// GEMM2: out = leaf_probs @ leaf_values (B = lv^T, n-major)
// ---------------------------------------------------------------------------
__global__ __launch_bounds__(512, 2)
void k_gemm2_mma(float* __restrict__ out)
{
    extern __shared__ char smem[];
    const uint32_t sb = smem_u32(smem);
    const int t    = threadIdx.x;
    const int warp = t >> 5;
    const int lane = t & 31;
    const int wm   = warp & 3;
    const int wn   = warp >> 2;
    const int m0   = blockIdx.x * 128;

    float acc[2][4][4];
#pragma unroll
    for (int i = 0; i < 2; i++)
#pragma unroll
        for (int j = 0; j < 4; j++)
#pragma unroll
            for (int q = 0; q < 4; q++) acc[i][j][q] = 0.0f;

    gemm_mainloop(acc, sb, &g_ps[0][0][0], &g_ps[1][0][0],
                  &g_lvs[0][0][0], &g_lvs[1][0][0], m0, 0, t);

    const int lr = lane >> 2;
    const int lc = (lane & 3) * 2;
#pragma unroll
    for (int mf = 0; mf < 2; mf++) {
        const int r0 = m0 + wm * 32 + mf * 16 + lr;
        const int r1 = r0 + 8;
        float* __restrict__ p0 = out + (size_t)r0 * OUT_DIM;
        float* __restrict__ p1 = out + (size_t)r1 * OUT_DIM;
#pragma unroll
        for (int nf = 0; nf < 4; nf++) {
            const int n = wn * 32 + nf * 8 + lc;
            const float* a4 = acc[mf][nf];
            *(float2*)(p0 + n) = make_float2(a4[0], a4[1]);
            *(float2*)(p1 + n) = make_float2(a4[2], a4[3]);
        }
    }
}

// ---------------------------------------------------------------------------
// Routing kernel: emits probs as bf16 hi/lo split
// ---------------------------------------------------------------------------
__global__ __launch_bounds__(128) void k_route() {
    __shared__ float buf[2][LEAVES];
    const int row = blockIdx.x;
    const int tid = threadIdx.x;
    const float* __restrict__ drow = g_dec + (size_t)row * NODES_PAD;

    if (tid == 0) buf[0][0] = 1.0f;
    __syncthreads();

    int cur = 0;
#pragma unroll
    for (int L = 0; L < TREE_DEPTH; L++) {
        int n = 1 << L;
        for (int i = tid; i < n; i += 128) {
            float dd = drow[n - 1 + i];
            float v  = buf[cur][i];
            buf[cur ^ 1][i]     = v * dd;
            buf[cur ^ 1][n + i] = v * (1.0f - dd);
        }
        __syncthreads();
        cur ^= 1;
    }

    __nv_bfloat16* __restrict__ ph = &g_ps[0][row][0];
    __nv_bfloat16* __restrict__ pl = &g_ps[1][row][0];
    for (int i = tid; i < LEAVES; i += 128) {
        float p = buf[cur][i];
        __nv_bfloat16 h = __float2bfloat16(p);
        __nv_bfloat16 l = __float2bfloat16(p - __bfloat162float(h));
        ph[i] = h;
        pl[i] = l;
    }
}

// ---------------------------------------------------------------------------
// Launch
// ---------------------------------------------------------------------------
extern "C" void kernel_launch(void* const* d_in, const int* in_sizes, int n_in,
                              void* d_out, int out_size)
{
    const float* x    = (const float*)d_in[0];
    const float* w    = (const float*)d_in[1];
    const float* bias = (const float*)d_in[2];
    const float* lv   = (const float*)d_in[3];
    const float* temp = (const float*)d_in[4];
    float* out = (float*)d_out;

    static int smem_set = 0;
    if (!smem_set) {
        cudaFuncSetAttribute(k_gemm1_mma, cudaFuncAttributeMaxDynamicSharedMemorySize, GMM_SMEM);
        cudaFuncSetAttribute(k_gemm2_mma, cudaFuncAttributeMaxDynamicSharedMemorySize, GMM_SMEM);
        smem_set = 1;
    }

    {
        size_t n4 = (size_t)BATCH * IN_DIM / 4;
        k_convert_x<<<(unsigned)((n4 + 255) / 256), 256>>>(x);
    }
    {
        size_t n4 = (size_t)NODES_PAD * IN_DIM / 4;
        k_convert_w<<<(unsigned)((n4 + 255) / 256), 256>>>(w);
    }
    k_convert_lv<<<(LEAVES * OUT_DIM + 255) / 256, 256>>>(lv);
    {
        dim3 grid(NODES_PAD / 128, BATCH / 128);   // (8, 128)
        k_gemm1_mma<<<grid, 512, GMM_SMEM>>>(bias, temp);
    }
    k_route<<<BATCH, 128>>>();
    k_gemm2_mma<<<BATCH / 128, 512, GMM_SMEM>>>(out);
}

// round 8
// speedup vs baseline: 1.4767x; 1.1166x over previous
#include <cuda_runtime.h>
#include <cuda_bf16.h>
#include <math.h>
#include <stdint.h>

#define BATCH   16384
#define IN_DIM  1024
#define NODES   1023
#define NODES_PAD 1024
#define LEAVES  1024
#define OUT_DIM 128
#define TREE_DEPTH 10

// ---------------------------------------------------------------------------
// Scratch
// ---------------------------------------------------------------------------
__device__ __nv_bfloat16 g_xs[2][BATCH][IN_DIM];      // hi/lo split of x  (64 MB)
__device__ __nv_bfloat16 g_ws[2][NODES_PAD][IN_DIM];  // hi/lo split of W  (4 MB)
__device__ float g_dec[(size_t)BATCH * NODES_PAD];    // 64 MB decisions
__device__ __nv_bfloat16 g_ps[2][BATCH][LEAVES];      // hi/lo split of leaf probs (64 MB)
__device__ __nv_bfloat16 g_lvs[2][OUT_DIM][LEAVES];   // hi/lo split of leaf_values^T (0.5 MB)
__device__ int   g_anymiss[BATCH];

__device__ __forceinline__ uint32_t smem_u32(const void* p) {
    uint32_t a;
    asm("{ .reg .u64 t; cvta.to.shared.u64 t, %1; cvt.u32.u64 %0, t; }" : "=r"(a) : "l"(p));
    return a;
}

// ---------------------------------------------------------------------------
// Converters
// ---------------------------------------------------------------------------
__global__ __launch_bounds__(256) void k_convert_x(const float* __restrict__ x) {
    size_t idx = (size_t)blockIdx.x * blockDim.x + threadIdx.x;   // float4 index
    if (idx * 4 >= (size_t)BATCH * IN_DIM) return;
    float4 v = ((const float4*)x)[idx];
    bool miss = (v.x != v.x) || (v.y != v.y) || (v.z != v.z) || (v.w != v.w);
    if (miss) atomicExch(&g_anymiss[(int)((idx * 4) / IN_DIM)], 1);
    float f[4] = { (v.x == v.x) ? v.x : 0.f, (v.y == v.y) ? v.y : 0.f,
                   (v.z == v.z) ? v.z : 0.f, (v.w == v.w) ? v.w : 0.f };
    __nv_bfloat16 hi[4], lo[4];
#pragma unroll
    for (int i = 0; i < 4; i++) {
        hi[i] = __float2bfloat16(f[i]);
        lo[i] = __float2bfloat16(f[i] - __bfloat162float(hi[i]));
    }
    *(uint2*)(&g_xs[0][0][0] + idx * 4) = *(uint2*)hi;
    *(uint2*)(&g_xs[1][0][0] + idx * 4) = *(uint2*)lo;
}

__global__ __launch_bounds__(256) void k_convert_w(const float* __restrict__ w) {
    size_t idx = (size_t)blockIdx.x * blockDim.x + threadIdx.x;
    if (idx * 4 >= (size_t)NODES_PAD * IN_DIM) return;
    size_t e = idx * 4;
    int n = (int)(e >> 10);
    float f[4] = {0.f, 0.f, 0.f, 0.f};
    if (n < NODES) { float4 v = *(const float4*)&w[e]; f[0] = v.x; f[1] = v.y; f[2] = v.z; f[3] = v.w; }
    __nv_bfloat16 hi[4], lo[4];
#pragma unroll
    for (int i = 0; i < 4; i++) {
        hi[i] = __float2bfloat16(f[i]);
        lo[i] = __float2bfloat16(f[i] - __bfloat162float(hi[i]));
    }
    *(uint2*)(&g_ws[0][0][0] + e) = *(uint2*)hi;
    *(uint2*)(&g_ws[1][0][0] + e) = *(uint2*)lo;
}

// leaf_values [k][n] fp32 -> transposed hi/lo bf16 [n][k]
__global__ __launch_bounds__(256) void k_convert_lv(const float* __restrict__ lv) {
    int idx = blockIdx.x * blockDim.x + threadIdx.x;
    if (idx >= LEAVES * OUT_DIM) return;
    int k = idx >> 7;
    int n = idx & 127;
    float f = lv[idx];
    __nv_bfloat16 hi = __float2bfloat16(f);
    __nv_bfloat16 lo = __float2bfloat16(f - __bfloat162float(hi));
    g_lvs[0][n][k] = hi;
    g_lvs[1][n][k] = lo;
}

// ---------------------------------------------------------------------------
// mma.sync machinery. Warp tile 32x32 (acc 32 regs). BK=64, 3-stage cp.async,
// serialized 3-pass hi/lo (K_eff = 3*1024 -> 48 iters). Mainloop unrolled by 3
// so stage indices are compile-time.
//   GEMM1: CTA 128x128, 512 thr, 16 warps (4M x 4N), 2 CTA/SM
//   GEMM2: CTA  64x128, 256 thr,  8 warps (2M x 4N), 3 CTA/SM
// ---------------------------------------------------------------------------
#define NSTAGES 3
#define BK 64

// swizzled offset for (row, 16B-chunk) in a row x 128B tile (8-way XOR)
__device__ __forceinline__ uint32_t swz(uint32_t base, int row, int chunk) {
    return base + row * 128 + ((chunk ^ (row & 7)) << 4);
}

__device__ __forceinline__ void cp16(uint32_t saddr, const void* gaddr) {
    asm volatile("cp.async.cg.shared.global [%0], [%1], 16;" :: "r"(saddr), "l"(gaddr));
}

__device__ __forceinline__ void ldsm_x4(uint32_t addr, uint32_t& r0, uint32_t& r1,
                                        uint32_t& r2, uint32_t& r3) {
    asm volatile("ldmatrix.sync.aligned.m8n8.x4.shared.b16 {%0,%1,%2,%3}, [%4];"
                 : "=r"(r0), "=r"(r1), "=r"(r2), "=r"(r3) : "r"(addr));
}

__device__ __forceinline__ void mma16816(float* d, const uint32_t* a, const uint32_t* b) {
    asm volatile(
        "mma.sync.aligned.m16n8k16.row.col.f32.bf16.bf16.f32 "
        "{%0,%1,%2,%3}, {%4,%5,%6,%7}, {%8,%9}, {%0,%1,%2,%3};"
        : "+f"(d[0]), "+f"(d[1]), "+f"(d[2]), "+f"(d[3])
        : "r"(a[0]), "r"(a[1]), "r"(a[2]), "r"(a[3]), "r"(b[0]), "r"(b[1]));
}

// issue one BK=64 stage. AROWS = A-tile rows, NT = threads.
template<int AROWS, int NT>
__device__ __forceinline__ void issue_stage_t(
    uint32_t sA,
    const __nv_bfloat16* __restrict__ Ah, const __nv_bfloat16* __restrict__ Al,
    const __nv_bfloat16* __restrict__ Bh, const __nv_bfloat16* __restrict__ Bl,
    int it, int m0, int n0, int t)
{
    const int seg = it >> 4;               // 0,1,2
    const int kb  = (it & 15) * BK;
    const __nv_bfloat16* Asrc = (seg < 2) ? Ah : Al;   // hi, hi, lo
    const __nv_bfloat16* Bsrc = (seg == 1) ? Bl : Bh;  // hi, lo, hi
    const uint32_t sB = sA + AROWS * 128;
#pragma unroll
    for (int i = 0; i < AROWS * 8 / NT; i++) {
        int idx = i * NT + t;
        int row = idx >> 3, c = idx & 7;
        cp16(swz(sA, row, c), Asrc + (size_t)(m0 + row) * 1024 + kb + c * 8);
    }
#pragma unroll
    for (int i = 0; i < 128 * 8 / NT; i++) {
        int idx = i * NT + t;
        int row = idx >> 3, c = idx & 7;
        cp16(swz(sB, row, c), Bsrc + (size_t)(n0 + row) * 1024 + kb + c * 8);
    }
    asm volatile("cp.async.commit_group;" ::: "memory");
}

// mainloop: accumulates 3-pass product into acc[2][4][4].
// MWARPS = warps along M (warp = wm + MWARPS*wn).
template<int AROWS, int NT, int MWARPS>
__device__ __forceinline__ void gemm_mainloop_t(
    float acc[2][4][4], uint32_t sb,
    const __nv_bfloat16* __restrict__ Ah, const __nv_bfloat16* __restrict__ Al,
    const __nv_bfloat16* __restrict__ Bh, const __nv_bfloat16* __restrict__ Bl,
    int m0, int n0, int t)
{
    constexpr int STAGE_B = (AROWS + 128) * 128;
    const int warp = t >> 5;
    const int lane = t & 31;
    const int wm   = warp & (MWARPS - 1);
    const int wn   = warp / MWARPS;        // 0..3
    const int a_r16 = lane & 15;
    const int lsub  = lane >> 4;
    const int b_row = ((lane >> 3) & 1) * 8 + (lane & 7);

    issue_stage_t<AROWS, NT>(sb,           Ah, Al, Bh, Bl, 0, m0, n0, t);
    issue_stage_t<AROWS, NT>(sb + STAGE_B, Ah, Al, Bh, Bl, 1, m0, n0, t);

    for (int ib = 0; ib < 16; ib++) {
#pragma unroll
        for (int s = 0; s < 3; s++) {
            const int it = ib * 3 + s;     // 0..47
            asm volatile("cp.async.wait_group %0;" :: "n"(NSTAGES - 2) : "memory");
            __syncthreads();

            if (it + 2 < 48) {
                constexpr int IS_STAGE[3] = {2, 0, 1};   // (s+2)%3
                issue_stage_t<AROWS, NT>(sb + IS_STAGE[s] * STAGE_B,
                                         Ah, Al, Bh, Bl, it + 2, m0, n0, t);
            } else {
                asm volatile("cp.async.commit_group;" ::: "memory");
            }

            const uint32_t sA = sb + s * STAGE_B;        // compile-time stage
            const uint32_t sB = sA + AROWS * 128;

#pragma unroll
            for (int h = 0; h < 4; h++) {                // four k16 slices
                const int ch = h * 2 + lsub;
                uint32_t a[2][4];
#pragma unroll
                for (int mf = 0; mf < 2; mf++) {
                    int row = wm * 32 + mf * 16 + a_r16;
                    ldsm_x4(swz(sA, row, ch), a[mf][0], a[mf][1], a[mf][2], a[mf][3]);
                }
                uint32_t b[4][2];
#pragma unroll
                for (int nb = 0; nb < 2; nb++) {
                    int row = wn * 32 + nb * 16 + b_row;
                    ldsm_x4(swz(sB, row, ch),
                            b[2 * nb][0], b[2 * nb + 1][0], b[2 * nb][1], b[2 * nb + 1][1]);
                }
#pragma unroll
                for (int mf = 0; mf < 2; mf++)
#pragma unroll
                    for (int nf = 0; nf < 4; nf++)
                        mma16816(acc[mf][nf], a[mf], b[nf]);
            }
        }
    }
}

#define G1_SMEM (NSTAGES * (128 + 128) * 128)   // 98304
#define G2_SMEM (NSTAGES * (64 + 128) * 128)    // 73728

// ---------------------------------------------------------------------------
// GEMM1: logits = x @ W^T + bias -> sigmoid -> g_dec
// ---------------------------------------------------------------------------
__global__ __launch_bounds__(512, 2)
void k_gemm1_mma(const float* __restrict__ bias, const float* __restrict__ temp)
{
    extern __shared__ char smem[];
    const uint32_t sb = smem_u32(smem);
    const int t    = threadIdx.x;
    const int warp = t >> 5;
    const int lane = t & 31;
    const int wm   = warp & 3;
    const int wn   = warp >> 2;
    const int m0   = blockIdx.y * 128;
    const int n0   = blockIdx.x * 128;

    float acc[2][4][4];
#pragma unroll
    for (int i = 0; i < 2; i++)
#pragma unroll
        for (int j = 0; j < 4; j++)
#pragma unroll
            for (int q = 0; q < 4; q++) acc[i][j][q] = 0.0f;

    gemm_mainloop_t<128, 512, 4>(acc, sb, &g_xs[0][0][0], &g_xs[1][0][0],
                                 &g_ws[0][0][0], &g_ws[1][0][0], m0, n0, t);

    const float invT = 1.0f / __ldg(temp);
    const int lr = lane >> 2;
    const int lc = (lane & 3) * 2;

#pragma unroll
    for (int mf = 0; mf < 2; mf++) {
        const int r0 = m0 + wm * 32 + mf * 16 + lr;
        const int r1 = r0 + 8;
        const int miss0 = g_anymiss[r0];
        const int miss1 = g_anymiss[r1];
        float* __restrict__ p0 = g_dec + (size_t)r0 * NODES_PAD;
        float* __restrict__ p1 = g_dec + (size_t)r1 * NODES_PAD;
#pragma unroll
        for (int nf = 0; nf < 4; nf++) {
            const int n = n0 + wn * 32 + nf * 8 + lc;
            const float bz0 = (n     < NODES) ? __ldg(&bias[n])     : 0.0f;
            const float bz1 = (n + 1 < NODES) ? __ldg(&bias[n + 1]) : 0.0f;
            const float* a4 = acc[mf][nf];
            float2 v0, v1;
            v0.x = miss0 ? 0.5f : 1.0f / (1.0f + __expf(-(a4[0] + bz0) * invT));
            v0.y = miss0 ? 0.5f : 1.0f / (1.0f + __expf(-(a4[1] + bz1) * invT));
            v1.x = miss1 ? 0.5f : 1.0f / (1.0f + __expf(-(a4[2] + bz0) * invT));
            v1.y = miss1 ? 0.5f : 1.0f / (1.0f + __expf(-(a4[3] + bz1) * invT));
            *(float2*)(p0 + n) = v0;
            *(float2*)(p1 + n) = v1;
        }
    }
}

// ---------------------------------------------------------------------------
// GEMM2: out = leaf_probs @ leaf_values (B = lv^T, n-major)
// CTA 64x128, 256 threads, grid 256.
// ---------------------------------------------------------------------------
__global__ __launch_bounds__(256, 3)
void k_gemm2_mma(float* __restrict__ out)
{
    extern __shared__ char smem[];
    const uint32_t sb = smem_u32(smem);
    const int t    = threadIdx.x;
    const int warp = t >> 5;
    const int lane = t & 31;
    const int wm   = warp & 1;
    const int wn   = warp >> 1;
    const int m0   = blockIdx.x * 64;

    float acc[2][4][4];
#pragma unroll
    for (int i = 0; i < 2; i++)
#pragma unroll
        for (int j = 0; j < 4; j++)
#pragma unroll
            for (int q = 0; q < 4; q++) acc[i][j][q] = 0.0f;

    gemm_mainloop_t<64, 256, 2>(acc, sb, &g_ps[0][0][0], &g_ps[1][0][0],
                                &g_lvs[0][0][0], &g_lvs[1][0][0], m0, 0, t);

    const int lr = lane >> 2;
    const int lc = (lane & 3) * 2;
#pragma unroll
    for (int mf = 0; mf < 2; mf++) {
        const int r0 = m0 + wm * 32 + mf * 16 + lr;
        const int r1 = r0 + 8;
        float* __restrict__ p0 = out + (size_t)r0 * OUT_DIM;
        float* __restrict__ p1 = out + (size_t)r1 * OUT_DIM;
#pragma unroll
        for (int nf = 0; nf < 4; nf++) {
            const int n = wn * 32 + nf * 8 + lc;
            const float* a4 = acc[mf][nf];
            *(float2*)(p0 + n) = make_float2(a4[0], a4[1]);
            *(float2*)(p1 + n) = make_float2(a4[2], a4[3]);
        }
    }
}

// ---------------------------------------------------------------------------
// Routing kernel: emits probs as bf16 hi/lo split
// ---------------------------------------------------------------------------
__global__ __launch_bounds__(128) void k_route() {
    __shared__ float buf[2][LEAVES];
    const int row = blockIdx.x;
    const int tid = threadIdx.x;
    const float* __restrict__ drow = g_dec + (size_t)row * NODES_PAD;

    if (tid == 0) buf[0][0] = 1.0f;
    __syncthreads();

    int cur = 0;
#pragma unroll
    for (int L = 0; L < TREE_DEPTH; L++) {
        int n = 1 << L;
        for (int i = tid; i < n; i += 128) {
            float dd = drow[n - 1 + i];
            float v  = buf[cur][i];
            buf[cur ^ 1][i]     = v * dd;
            buf[cur ^ 1][n + i] = v * (1.0f - dd);
        }
        __syncthreads();
        cur ^= 1;
    }

    __nv_bfloat16* __restrict__ ph = &g_ps[0][row][0];
    __nv_bfloat16* __restrict__ pl = &g_ps[1][row][0];
    for (int i = tid; i < LEAVES; i += 128) {
        float p = buf[cur][i];
        __nv_bfloat16 h = __float2bfloat16(p);
        __nv_bfloat16 l = __float2bfloat16(p - __bfloat162float(h));
        ph[i] = h;
        pl[i] = l;
    }
}

// ---------------------------------------------------------------------------
// Launch
// ---------------------------------------------------------------------------
extern "C" void kernel_launch(void* const* d_in, const int* in_sizes, int n_in,
                              void* d_out, int out_size)
{
    const float* x    = (const float*)d_in[0];
    const float* w    = (const float*)d_in[1];
    const float* bias = (const float*)d_in[2];
    const float* lv   = (const float*)d_in[3];
    const float* temp = (const float*)d_in[4];
    float* out = (float*)d_out;

    static int smem_set = 0;
    if (!smem_set) {
        cudaFuncSetAttribute(k_gemm1_mma, cudaFuncAttributeMaxDynamicSharedMemorySize, G1_SMEM);
        cudaFuncSetAttribute(k_gemm2_mma, cudaFuncAttributeMaxDynamicSharedMemorySize, G2_SMEM);
        smem_set = 1;
    }

    {
        size_t n4 = (size_t)BATCH * IN_DIM / 4;
        k_convert_x<<<(unsigned)((n4 + 255) / 256), 256>>>(x);
    }
    {
        size_t n4 = (size_t)NODES_PAD * IN_DIM / 4;
        k_convert_w<<<(unsigned)((n4 + 255) / 256), 256>>>(w);
    }
    k_convert_lv<<<(LEAVES * OUT_DIM + 255) / 256, 256>>>(lv);
    {
        dim3 grid(NODES_PAD / 128, BATCH / 128);   // (8, 128)
        k_gemm1_mma<<<grid, 512, G1_SMEM>>>(bias, temp);
    }
    k_route<<<BATCH, 128>>>();
    k_gemm2_mma<<<BATCH / 64, 256, G2_SMEM>>>(out);
}

// round 9
// speedup vs baseline: 1.5043x; 1.0187x over previous
#include <cuda_runtime.h>
#include <cuda_bf16.h>
#include <math.h>
#include <stdint.h>

#define BATCH   16384
#define IN_DIM  1024
#define NODES   1023
#define NODES_PAD 1024
#define LEAVES  1024
#define OUT_DIM 128
#define TREE_DEPTH 10

// ---------------------------------------------------------------------------
// Scratch
// ---------------------------------------------------------------------------
__device__ __nv_bfloat16 g_xs[2][BATCH][IN_DIM];      // hi/lo split of x  (64 MB)
__device__ __nv_bfloat16 g_ws[2][NODES_PAD][IN_DIM];  // hi/lo split of W  (4 MB)
__device__ float g_dec[(size_t)BATCH * NODES_PAD];    // 64 MB decisions
__device__ __nv_bfloat16 g_ps[2][BATCH][LEAVES];      // hi/lo split of leaf probs (64 MB)
__device__ __nv_bfloat16 g_lvs[2][OUT_DIM][LEAVES];   // hi/lo split of leaf_values^T (0.5 MB)
__device__ int   g_anymiss[BATCH];

__device__ __forceinline__ uint32_t smem_u32(const void* p) {
    uint32_t a;
    asm("{ .reg .u64 t; cvta.to.shared.u64 t, %1; cvt.u32.u64 %0, t; }" : "=r"(a) : "l"(p));
    return a;
}

// ---------------------------------------------------------------------------
// Converters
// ---------------------------------------------------------------------------
__global__ __launch_bounds__(256) void k_convert_x(const float* __restrict__ x) {
    size_t idx = (size_t)blockIdx.x * blockDim.x + threadIdx.x;   // float4 index
    if (idx * 4 >= (size_t)BATCH * IN_DIM) return;
    float4 v = ((const float4*)x)[idx];
    bool miss = (v.x != v.x) || (v.y != v.y) || (v.z != v.z) || (v.w != v.w);
    if (miss) atomicExch(&g_anymiss[(int)((idx * 4) / IN_DIM)], 1);
    float f[4] = { (v.x == v.x) ? v.x : 0.f, (v.y == v.y) ? v.y : 0.f,
                   (v.z == v.z) ? v.z : 0.f, (v.w == v.w) ? v.w : 0.f };
    __nv_bfloat16 hi[4], lo[4];
#pragma unroll
    for (int i = 0; i < 4; i++) {
        hi[i] = __float2bfloat16(f[i]);
        lo[i] = __float2bfloat16(f[i] - __bfloat162float(hi[i]));
    }
    *(uint2*)(&g_xs[0][0][0] + idx * 4) = *(uint2*)hi;
    *(uint2*)(&g_xs[1][0][0] + idx * 4) = *(uint2*)lo;
}

// W (1024 blocks) + leaf_values^T (512 blocks) in one launch
#define WB_BLOCKS ((NODES_PAD * IN_DIM / 4 + 255) / 256)           // 1024
#define LV_BLOCKS ((LEAVES * OUT_DIM + 255) / 256)                 // 512

__global__ __launch_bounds__(256) void k_convert_wlv(const float* __restrict__ w,
                                                     const float* __restrict__ lv) {
    if (blockIdx.x < WB_BLOCKS) {
        size_t idx = (size_t)blockIdx.x * blockDim.x + threadIdx.x;
        if (idx * 4 >= (size_t)NODES_PAD * IN_DIM) return;
        size_t e = idx * 4;
        int n = (int)(e >> 10);
        float f[4] = {0.f, 0.f, 0.f, 0.f};
        if (n < NODES) { float4 v = *(const float4*)&w[e]; f[0] = v.x; f[1] = v.y; f[2] = v.z; f[3] = v.w; }
        __nv_bfloat16 hi[4], lo[4];
#pragma unroll
        for (int i = 0; i < 4; i++) {
            hi[i] = __float2bfloat16(f[i]);
            lo[i] = __float2bfloat16(f[i] - __bfloat162float(hi[i]));
        }
        *(uint2*)(&g_ws[0][0][0] + e) = *(uint2*)hi;
        *(uint2*)(&g_ws[1][0][0] + e) = *(uint2*)lo;
    } else {
        int idx = (blockIdx.x - WB_BLOCKS) * blockDim.x + threadIdx.x;
        if (idx >= LEAVES * OUT_DIM) return;
        int k = idx >> 7;
        int n = idx & 127;
        float f = lv[idx];
        __nv_bfloat16 hi = __float2bfloat16(f);
        __nv_bfloat16 lo = __float2bfloat16(f - __bfloat162float(hi));
        g_lvs[0][n][k] = hi;
        g_lvs[1][n][k] = lo;
    }
}

// ---------------------------------------------------------------------------
// mma.sync machinery. Warp tile 32x32 (acc 32 regs). BK=64, 3-stage cp.async,
// serialized 3-pass hi/lo (K_eff = 3*1024 -> 48 iters), unroll-by-3 so stage
// indices are compile-time. cp.async offsets precomputed per thread.
//   GEMM1: CTA 128x128, 512 thr, 16 warps (4M x 4N), 2 CTA/SM
//   GEMM2: CTA  64x128, 256 thr,  8 warps (2M x 4N), 3 CTA/SM
// ---------------------------------------------------------------------------
#define NSTAGES 3
#define BK 64

__device__ __forceinline__ uint32_t swz(uint32_t base, int row, int chunk) {
    return base + row * 128 + ((chunk ^ (row & 7)) << 4);
}

__device__ __forceinline__ void cp16(uint32_t saddr, const void* gaddr) {
    asm volatile("cp.async.cg.shared.global [%0], [%1], 16;" :: "r"(saddr), "l"(gaddr));
}

__device__ __forceinline__ void ldsm_x4(uint32_t addr, uint32_t& r0, uint32_t& r1,
                                        uint32_t& r2, uint32_t& r3) {
    asm volatile("ldmatrix.sync.aligned.m8n8.x4.shared.b16 {%0,%1,%2,%3}, [%4];"
                 : "=r"(r0), "=r"(r1), "=r"(r2), "=r"(r3) : "r"(addr));
}

__device__ __forceinline__ void mma16816(float* d, const uint32_t* a, const uint32_t* b) {
    asm volatile(
        "mma.sync.aligned.m16n8k16.row.col.f32.bf16.bf16.f32 "
        "{%0,%1,%2,%3}, {%4,%5,%6,%7}, {%8,%9}, {%0,%1,%2,%3};"
        : "+f"(d[0]), "+f"(d[1]), "+f"(d[2]), "+f"(d[3])
        : "r"(a[0]), "r"(a[1]), "r"(a[2]), "r"(a[3]), "r"(b[0]), "r"(b[1]));
}

// Per-thread precomputed cp.async offsets (elements, fits uint32)
template<int AROWS, int NT>
struct CpOffs {
    static constexpr int ACP = AROWS * 8 / NT;
    static constexpr int BCP = 128 * 8 / NT;
    uint32_t a_s[ACP], b_s[BCP];   // smem offsets (within stage, pre-swizzle applied)
    uint32_t a_g[ACP], b_g[BCP];   // global element offsets (excl. kb)
    __device__ __forceinline__ void init(int m0, int n0, int t) {
#pragma unroll
        for (int i = 0; i < ACP; i++) {
            int idx = i * NT + t;
            int row = idx >> 3, c = idx & 7;
            a_s[i] = swz(0, row, c);
            a_g[i] = (uint32_t)(m0 + row) * 1024u + (uint32_t)c * 8u;
        }
#pragma unroll
        for (int i = 0; i < BCP; i++) {
            int idx = i * NT + t;
            int row = idx >> 3, c = idx & 7;
            b_s[i] = swz(0, row, c);
            b_g[i] = (uint32_t)(n0 + row) * 1024u + (uint32_t)c * 8u;
        }
    }
};

template<int AROWS, int NT>
__device__ __forceinline__ void issue_stage_t(
    uint32_t sA, const CpOffs<AROWS, NT>& o,
    const __nv_bfloat16* __restrict__ Ah, const __nv_bfloat16* __restrict__ Al,
    const __nv_bfloat16* __restrict__ Bh, const __nv_bfloat16* __restrict__ Bl,
    int it)
{
    const int seg = it >> 4;               // 0,1,2
    const uint32_t kb = (uint32_t)(it & 15) * BK;
    const __nv_bfloat16* Asrc = (seg < 2) ? Ah : Al;   // hi, hi, lo
    const __nv_bfloat16* Bsrc = (seg == 1) ? Bl : Bh;  // hi, lo, hi
    const uint32_t sB = sA + AROWS * 128;
#pragma unroll
    for (int i = 0; i < CpOffs<AROWS, NT>::ACP; i++)
        cp16(sA + o.a_s[i], Asrc + o.a_g[i] + kb);
#pragma unroll
    for (int i = 0; i < CpOffs<AROWS, NT>::BCP; i++)
        cp16(sB + o.b_s[i], Bsrc + o.b_g[i] + kb);
    asm volatile("cp.async.commit_group;" ::: "memory");
}

template<int AROWS, int NT, int MWARPS>
__device__ __forceinline__ void gemm_mainloop_t(
    float acc[2][4][4], uint32_t sb,
    const __nv_bfloat16* __restrict__ Ah, const __nv_bfloat16* __restrict__ Al,
    const __nv_bfloat16* __restrict__ Bh, const __nv_bfloat16* __restrict__ Bl,
    int m0, int n0, int t)
{
    constexpr int STAGE_B = (AROWS + 128) * 128;
    const int warp = t >> 5;
    const int lane = t & 31;
    const int wm   = warp & (MWARPS - 1);
    const int wn   = warp / MWARPS;        // 0..3
    const int a_r16 = lane & 15;
    const int lsub  = lane >> 4;
    const int b_row = ((lane >> 3) & 1) * 8 + (lane & 7);

    CpOffs<AROWS, NT> offs;
    offs.init(m0, n0, t);

    issue_stage_t<AROWS, NT>(sb,           offs, Ah, Al, Bh, Bl, 0);
    issue_stage_t<AROWS, NT>(sb + STAGE_B, offs, Ah, Al, Bh, Bl, 1);

    for (int ib = 0; ib < 16; ib++) {
#pragma unroll
        for (int s = 0; s < 3; s++) {
            const int it = ib * 3 + s;     // 0..47
            asm volatile("cp.async.wait_group %0;" :: "n"(NSTAGES - 2) : "memory");
            __syncthreads();

            if (it + 2 < 48) {
                constexpr int IS_STAGE[3] = {2, 0, 1};   // (s+2)%3
                issue_stage_t<AROWS, NT>(sb + IS_STAGE[s] * STAGE_B,
                                         offs, Ah, Al, Bh, Bl, it + 2);
            } else {
                asm volatile("cp.async.commit_group;" ::: "memory");
            }

            const uint32_t sA = sb + s * STAGE_B;        // compile-time stage
            const uint32_t sB = sA + AROWS * 128;

#pragma unroll
            for (int h = 0; h < 4; h++) {                // four k16 slices
                const int ch = h * 2 + lsub;
                uint32_t a[2][4];
#pragma unroll
                for (int mf = 0; mf < 2; mf++) {
                    int row = wm * 32 + mf * 16 + a_r16;
                    ldsm_x4(swz(sA, row, ch), a[mf][0], a[mf][1], a[mf][2], a[mf][3]);
                }
                uint32_t b[4][2];
#pragma unroll
                for (int nb = 0; nb < 2; nb++) {
                    int row = wn * 32 + nb * 16 + b_row;
                    ldsm_x4(swz(sB, row, ch),
                            b[2 * nb][0], b[2 * nb + 1][0], b[2 * nb][1], b[2 * nb + 1][1]);
                }
#pragma unroll
                for (int mf = 0; mf < 2; mf++)
#pragma unroll
                    for (int nf = 0; nf < 4; nf++)
                        mma16816(acc[mf][nf], a[mf], b[nf]);
            }
        }
    }
}

#define G1_SMEM (NSTAGES * (128 + 128) * 128)   // 98304
#define G2_SMEM (NSTAGES * (64 + 128) * 128)    // 73728

// ---------------------------------------------------------------------------
// GEMM1: logits = x @ W^T + bias -> sigmoid -> g_dec
// ---------------------------------------------------------------------------
__global__ __launch_bounds__(512, 2)
void k_gemm1_mma(const float* __restrict__ bias, const float* __restrict__ temp)
{
    extern __shared__ char smem[];
    const uint32_t sb = smem_u32(smem);
    const int t    = threadIdx.x;
    const int warp = t >> 5;
    const int lane = t & 31;
    const int wm   = warp & 3;
    const int wn   = warp >> 2;
    const int m0   = blockIdx.y * 128;
    const int n0   = blockIdx.x * 128;

    float acc[2][4][4];
#pragma unroll
    for (int i = 0; i < 2; i++)
#pragma unroll
        for (int j = 0; j < 4; j++)
#pragma unroll
            for (int q = 0; q < 4; q++) acc[i][j][q] = 0.0f;

    gemm_mainloop_t<128, 512, 4>(acc, sb, &g_xs[0][0][0], &g_xs[1][0][0],
                                 &g_ws[0][0][0], &g_ws[1][0][0], m0, n0, t);

    const float invT = 1.0f / __ldg(temp);
    const int lr = lane >> 2;
    const int lc = (lane & 3) * 2;

#pragma unroll
    for (int mf = 0; mf < 2; mf++) {
        const int r0 = m0 + wm * 32 + mf * 16 + lr;
        const int r1 = r0 + 8;
        const int miss0 = g_anymiss[r0];
        const int miss1 = g_anymiss[r1];
        float* __restrict__ p0 = g_dec + (size_t)r0 * NODES_PAD;
        float* __restrict__ p1 = g_dec + (size_t)r1 * NODES_PAD;
#pragma unroll
        for (int nf = 0; nf < 4; nf++) {
            const int n = n0 + wn * 32 + nf * 8 + lc;
            const float bz0 = (n     < NODES) ? __ldg(&bias[n])     : 0.0f;
            const float bz1 = (n + 1 < NODES) ? __ldg(&bias[n + 1]) : 0.0f;
            const float* a4 = acc[mf][nf];
            float2 v0, v1;
            v0.x = miss0 ? 0.5f : 1.0f / (1.0f + __expf(-(a4[0] + bz0) * invT));
            v0.y = miss0 ? 0.5f : 1.0f / (1.0f + __expf(-(a4[1] + bz1) * invT));
            v1.x = miss1 ? 0.5f : 1.0f / (1.0f + __expf(-(a4[2] + bz0) * invT));
            v1.y = miss1 ? 0.5f : 1.0f / (1.0f + __expf(-(a4[3] + bz1) * invT));
            *(float2*)(p0 + n) = v0;
            *(float2*)(p1 + n) = v1;
        }
    }
}

// ---------------------------------------------------------------------------
// GEMM2: out = leaf_probs @ leaf_values (B = lv^T, n-major)
// ---------------------------------------------------------------------------
__global__ __launch_bounds__(256, 3)
void k_gemm2_mma(float* __restrict__ out)
{
    extern __shared__ char smem[];
    const uint32_t sb = smem_u32(smem);
    const int t    = threadIdx.x;
    const int warp = t >> 5;
    const int lane = t & 31;
    const int wm   = warp & 1;
    const int wn   = warp >> 1;
    const int m0   = blockIdx.x * 64;

    float acc[2][4][4];
#pragma unroll
    for (int i = 0; i < 2; i++)
#pragma unroll
        for (int j = 0; j < 4; j++)
#pragma unroll
            for (int q = 0; q < 4; q++) acc[i][j][q] = 0.0f;

    gemm_mainloop_t<64, 256, 2>(acc, sb, &g_ps[0][0][0], &g_ps[1][0][0],
                                &g_lvs[0][0][0], &g_lvs[1][0][0], m0, 0, t);

    const int lr = lane >> 2;
    const int lc = (lane & 3) * 2;
#pragma unroll
    for (int mf = 0; mf < 2; mf++) {
        const int r0 = m0 + wm * 32 + mf * 16 + lr;
        const int r1 = r0 + 8;
        float* __restrict__ p0 = out + (size_t)r0 * OUT_DIM;
        float* __restrict__ p1 = out + (size_t)r1 * OUT_DIM;
#pragma unroll
        for (int nf = 0; nf < 4; nf++) {
            const int n = wn * 32 + nf * 8 + lc;
            const float* a4 = acc[mf][nf];
            *(float2*)(p0 + n) = make_float2(a4[0], a4[1]);
            *(float2*)(p1 + n) = make_float2(a4[2], a4[3]);
        }
    }
}

// ---------------------------------------------------------------------------
// Routing kernel: emits probs as bf16 hi/lo split, vectorized 8B stores
// ---------------------------------------------------------------------------
__global__ __launch_bounds__(128) void k_route() {
    __shared__ float buf[2][LEAVES];
    const int row = blockIdx.x;
    const int tid = threadIdx.x;
    const float* __restrict__ drow = g_dec + (size_t)row * NODES_PAD;

    if (tid == 0) buf[0][0] = 1.0f;
    __syncthreads();

    int cur = 0;
#pragma unroll
    for (int L = 0; L < TREE_DEPTH; L++) {
        int n = 1 << L;
        for (int i = tid; i < n; i += 128) {
            float dd = drow[n - 1 + i];
            float v  = buf[cur][i];
            buf[cur ^ 1][i]     = v * dd;
            buf[cur ^ 1][n + i] = v * (1.0f - dd);
        }
        __syncthreads();
        cur ^= 1;
    }

    // 4 leaves per thread -> one uint2 (8B) store per array, fully coalesced
    __nv_bfloat16* __restrict__ ph = &g_ps[0][row][0];
    __nv_bfloat16* __restrict__ pl = &g_ps[1][row][0];
    {
        const int i0 = tid * 4;            // 128 thr * 4 = 512; two rounds
#pragma unroll
        for (int r = 0; r < 2; r++) {
            int i = i0 + r * 512;
            __nv_bfloat16 h[4], l[4];
#pragma unroll
            for (int q = 0; q < 4; q++) {
                float p = buf[cur][i + q];
                h[q] = __float2bfloat16(p);
                l[q] = __float2bfloat16(p - __bfloat162float(h[q]));
            }
            *(uint2*)(ph + i) = *(uint2*)h;
            *(uint2*)(pl + i) = *(uint2*)l;
        }
    }
}

// ---------------------------------------------------------------------------
// Launch
// ---------------------------------------------------------------------------
extern "C" void kernel_launch(void* const* d_in, const int* in_sizes, int n_in,
                              void* d_out, int out_size)
{
    const float* x    = (const float*)d_in[0];
    const float* w    = (const float*)d_in[1];
    const float* bias = (const float*)d_in[2];
    const float* lv   = (const float*)d_in[3];
    const float* temp = (const float*)d_in[4];
    float* out = (float*)d_out;

    static int smem_set = 0;
    if (!smem_set) {
        cudaFuncSetAttribute(k_gemm1_mma, cudaFuncAttributeMaxDynamicSharedMemorySize, G1_SMEM);
        cudaFuncSetAttribute(k_gemm2_mma, cudaFuncAttributeMaxDynamicSharedMemorySize, G2_SMEM);
        smem_set = 1;
    }

    {
        size_t n4 = (size_t)BATCH * IN_DIM / 4;
        k_convert_x<<<(unsigned)((n4 + 255) / 256), 256>>>(x);
    }
    k_convert_wlv<<<WB_BLOCKS + LV_BLOCKS, 256>>>(w, lv);
    {
        dim3 grid(NODES_PAD / 128, BATCH / 128);   // (8, 128)
        k_gemm1_mma<<<grid, 512, G1_SMEM>>>(bias, temp);
    }
    k_route<<<BATCH, 128>>>();
    k_gemm2_mma<<<BATCH / 64, 256, G2_SMEM>>>(out);
}

// round 10
// speedup vs baseline: 1.6225x; 1.0785x over previous
#include <cuda_runtime.h>
#include <cuda_bf16.h>
#include <math.h>
#include <stdint.h>

#define BATCH   16384
#define IN_DIM  1024
#define NODES   1023
#define NODES_PAD 1024
#define LEAVES  1024
#define OUT_DIM 128
#define TREE_DEPTH 10

// ---------------------------------------------------------------------------
// Scratch
// ---------------------------------------------------------------------------
__device__ __nv_bfloat16 g_xs[2][BATCH][IN_DIM];      // hi/lo split of x  (64 MB)
__device__ __nv_bfloat16 g_ws[2][NODES_PAD][IN_DIM];  // hi/lo split of W  (4 MB)
__device__ float g_dec[(size_t)BATCH * NODES_PAD];    // 64 MB decisions
__device__ __nv_bfloat16 g_ps[2][BATCH][LEAVES];      // hi/lo split of leaf probs (64 MB)
__device__ __nv_bfloat16 g_lvs[2][OUT_DIM][LEAVES];   // hi/lo split of leaf_values^T (0.5 MB)
__device__ int   g_anymiss[BATCH];

__device__ __forceinline__ uint32_t smem_u32(const void* p) {
    uint32_t a;
    asm("{ .reg .u64 t; cvta.to.shared.u64 t, %1; cvt.u32.u64 %0, t; }" : "=r"(a) : "l"(p));
    return a;
}

// ---------------------------------------------------------------------------
// Unified converter: x (16384 blocks) | W (1024) | leaf_values^T (512)
// ---------------------------------------------------------------------------
#define XB_BLOCKS ((int)((size_t)BATCH * IN_DIM / 4 / 256))        // 16384
#define WB_BLOCKS ((NODES_PAD * IN_DIM / 4 + 255) / 256)           // 1024
#define LV_BLOCKS ((LEAVES * OUT_DIM + 255) / 256)                 // 512

__global__ __launch_bounds__(256) void k_convert_all(const float* __restrict__ x,
                                                     const float* __restrict__ w,
                                                     const float* __restrict__ lv) {
    if (blockIdx.x < XB_BLOCKS) {
        size_t idx = (size_t)blockIdx.x * blockDim.x + threadIdx.x;   // float4 index
        float4 v = ((const float4*)x)[idx];
        bool miss = (v.x != v.x) || (v.y != v.y) || (v.z != v.z) || (v.w != v.w);
        if (miss) atomicExch(&g_anymiss[(int)((idx * 4) / IN_DIM)], 1);
        float f[4] = { (v.x == v.x) ? v.x : 0.f, (v.y == v.y) ? v.y : 0.f,
                       (v.z == v.z) ? v.z : 0.f, (v.w == v.w) ? v.w : 0.f };
        __nv_bfloat16 hi[4], lo[4];
#pragma unroll
        for (int i = 0; i < 4; i++) {
            hi[i] = __float2bfloat16(f[i]);
            lo[i] = __float2bfloat16(f[i] - __bfloat162float(hi[i]));
        }
        *(uint2*)(&g_xs[0][0][0] + idx * 4) = *(uint2*)hi;
        *(uint2*)(&g_xs[1][0][0] + idx * 4) = *(uint2*)lo;
    } else if (blockIdx.x < XB_BLOCKS + WB_BLOCKS) {
        size_t idx = (size_t)(blockIdx.x - XB_BLOCKS) * blockDim.x + threadIdx.x;
        size_t e = idx * 4;
        int n = (int)(e >> 10);
        float f[4] = {0.f, 0.f, 0.f, 0.f};
        if (n < NODES) { float4 v = *(const float4*)&w[e]; f[0] = v.x; f[1] = v.y; f[2] = v.z; f[3] = v.w; }
        __nv_bfloat16 hi[4], lo[4];
#pragma unroll
        for (int i = 0; i < 4; i++) {
            hi[i] = __float2bfloat16(f[i]);
            lo[i] = __float2bfloat16(f[i] - __bfloat162float(hi[i]));
        }
        *(uint2*)(&g_ws[0][0][0] + e) = *(uint2*)hi;
        *(uint2*)(&g_ws[1][0][0] + e) = *(uint2*)lo;
    } else {
        int idx = (blockIdx.x - XB_BLOCKS - WB_BLOCKS) * blockDim.x + threadIdx.x;
        if (idx >= LEAVES * OUT_DIM) return;
        int k = idx >> 7;
        int n = idx & 127;
        float f = lv[idx];
        __nv_bfloat16 hi = __float2bfloat16(f);
        __nv_bfloat16 lo = __float2bfloat16(f - __bfloat162float(hi));
        g_lvs[0][n][k] = hi;
        g_lvs[1][n][k] = lo;
    }
}

// ---------------------------------------------------------------------------
// mma.sync machinery. Warp tile 32x32 (acc 32 regs). BK=64, 3-stage cp.async,
// serialized 3-pass hi/lo (K_eff = 3*1024 -> 48 iters), unroll-by-3 so stage
// indices are compile-time. cp.async offsets precomputed per thread.
//   GEMM1: CTA 128x128, 512 thr, 16 warps (4M x 4N), 2 CTA/SM
//   GEMM2: CTA  64x128, 256 thr,  8 warps (2M x 4N), 3 CTA/SM
// ---------------------------------------------------------------------------
#define NSTAGES 3
#define BK 64

__device__ __forceinline__ uint32_t swz(uint32_t base, int row, int chunk) {
    return base + row * 128 + ((chunk ^ (row & 7)) << 4);
}

__device__ __forceinline__ void cp16(uint32_t saddr, const void* gaddr) {
    asm volatile("cp.async.cg.shared.global [%0], [%1], 16;" :: "r"(saddr), "l"(gaddr));
}

__device__ __forceinline__ void ldsm_x4(uint32_t addr, uint32_t& r0, uint32_t& r1,
                                        uint32_t& r2, uint32_t& r3) {
    asm volatile("ldmatrix.sync.aligned.m8n8.x4.shared.b16 {%0,%1,%2,%3}, [%4];"
                 : "=r"(r0), "=r"(r1), "=r"(r2), "=r"(r3) : "r"(addr));
}

__device__ __forceinline__ void mma16816(float* d, const uint32_t* a, const uint32_t* b) {
    asm volatile(
        "mma.sync.aligned.m16n8k16.row.col.f32.bf16.bf16.f32 "
        "{%0,%1,%2,%3}, {%4,%5,%6,%7}, {%8,%9}, {%0,%1,%2,%3};"
        : "+f"(d[0]), "+f"(d[1]), "+f"(d[2]), "+f"(d[3])
        : "r"(a[0]), "r"(a[1]), "r"(a[2]), "r"(a[3]), "r"(b[0]), "r"(b[1]));
}

// Per-thread precomputed cp.async offsets
template<int AROWS, int NT>
struct CpOffs {
    static constexpr int ACP = AROWS * 8 / NT;
    static constexpr int BCP = 128 * 8 / NT;
    uint32_t a_s[ACP], b_s[BCP];
    uint32_t a_g[ACP], b_g[BCP];
    __device__ __forceinline__ void init(int m0, int n0, int t) {
#pragma unroll
        for (int i = 0; i < ACP; i++) {
            int idx = i * NT + t;
            int row = idx >> 3, c = idx & 7;
            a_s[i] = swz(0, row, c);
            a_g[i] = (uint32_t)(m0 + row) * 1024u + (uint32_t)c * 8u;
        }
#pragma unroll
        for (int i = 0; i < BCP; i++) {
            int idx = i * NT + t;
            int row = idx >> 3, c = idx & 7;
            b_s[i] = swz(0, row, c);
            b_g[i] = (uint32_t)(n0 + row) * 1024u + (uint32_t)c * 8u;
        }
    }
};

template<int AROWS, int NT>
__device__ __forceinline__ void issue_stage_t(
    uint32_t sA, const CpOffs<AROWS, NT>& o,
    const __nv_bfloat16* __restrict__ Ah, const __nv_bfloat16* __restrict__ Al,
    const __nv_bfloat16* __restrict__ Bh, const __nv_bfloat16* __restrict__ Bl,
    int it)
{
    const int seg = it >> 4;               // 0,1,2
    const uint32_t kb = (uint32_t)(it & 15) * BK;
    const __nv_bfloat16* Asrc = (seg < 2) ? Ah : Al;   // hi, hi, lo
    const __nv_bfloat16* Bsrc = (seg == 1) ? Bl : Bh;  // hi, lo, hi
    const uint32_t sB = sA + AROWS * 128;
#pragma unroll
    for (int i = 0; i < CpOffs<AROWS, NT>::ACP; i++)
        cp16(sA + o.a_s[i], Asrc + o.a_g[i] + kb);
#pragma unroll
    for (int i = 0; i < CpOffs<AROWS, NT>::BCP; i++)
        cp16(sB + o.b_s[i], Bsrc + o.b_g[i] + kb);
    asm volatile("cp.async.commit_group;" ::: "memory");
}

template<int AROWS, int NT, int MWARPS>
__device__ __forceinline__ void gemm_mainloop_t(
    float acc[2][4][4], uint32_t sb,
    const __nv_bfloat16* __restrict__ Ah, const __nv_bfloat16* __restrict__ Al,
    const __nv_bfloat16* __restrict__ Bh, const __nv_bfloat16* __restrict__ Bl,
    int m0, int n0, int t)
{
    constexpr int STAGE_B = (AROWS + 128) * 128;
    const int warp = t >> 5;
    const int lane = t & 31;
    const int wm   = warp & (MWARPS - 1);
    const int wn   = warp / MWARPS;
    const int a_r16 = lane & 15;
    const int lsub  = lane >> 4;
    const int b_row = ((lane >> 3) & 1) * 8 + (lane & 7);

    CpOffs<AROWS, NT> offs;
    offs.init(m0, n0, t);

    issue_stage_t<AROWS, NT>(sb,           offs, Ah, Al, Bh, Bl, 0);
    issue_stage_t<AROWS, NT>(sb + STAGE_B, offs, Ah, Al, Bh, Bl, 1);

    for (int ib = 0; ib < 16; ib++) {
#pragma unroll
        for (int s = 0; s < 3; s++) {
            const int it = ib * 3 + s;     // 0..47
            asm volatile("cp.async.wait_group %0;" :: "n"(NSTAGES - 2) : "memory");
            __syncthreads();

            if (it + 2 < 48) {
                constexpr int IS_STAGE[3] = {2, 0, 1};   // (s+2)%3
                issue_stage_t<AROWS, NT>(sb + IS_STAGE[s] * STAGE_B,
                                         offs, Ah, Al, Bh, Bl, it + 2);
            } else {
                asm volatile("cp.async.commit_group;" ::: "memory");
            }

            const uint32_t sA = sb + s * STAGE_B;
            const uint32_t sB = sA + AROWS * 128;

#pragma unroll
            for (int h = 0; h < 4; h++) {
                const int ch = h * 2 + lsub;
                uint32_t a[2][4];
#pragma unroll
                for (int mf = 0; mf < 2; mf++) {
                    int row = wm * 32 + mf * 16 + a_r16;
                    ldsm_x4(swz(sA, row, ch), a[mf][0], a[mf][1], a[mf][2], a[mf][3]);
                }
                uint32_t b[4][2];
#pragma unroll
                for (int nb = 0; nb < 2; nb++) {
                    int row = wn * 32 + nb * 16 + b_row;
                    ldsm_x4(swz(sB, row, ch),
                            b[2 * nb][0], b[2 * nb + 1][0], b[2 * nb][1], b[2 * nb + 1][1]);
                }
#pragma unroll
                for (int mf = 0; mf < 2; mf++)
#pragma unroll
                    for (int nf = 0; nf < 4; nf++)
                        mma16816(acc[mf][nf], a[mf], b[nf]);
            }
        }
    }
}

#define G1_SMEM (NSTAGES * (128 + 128) * 128)   // 98304
#define G2_SMEM (NSTAGES * (64 + 128) * 128)    // 73728

// ---------------------------------------------------------------------------
// GEMM1: logits = x @ W^T + bias -> sigmoid -> g_dec
// ---------------------------------------------------------------------------
__global__ __launch_bounds__(512, 2)
void k_gemm1_mma(const float* __restrict__ bias, const float* __restrict__ temp)
{
    extern __shared__ char smem[];
    const uint32_t sb = smem_u32(smem);
    const int t    = threadIdx.x;
    const int warp = t >> 5;
    const int lane = t & 31;
    const int wm   = warp & 3;
    const int wn   = warp >> 2;
    const int m0   = blockIdx.y * 128;
    const int n0   = blockIdx.x * 128;

    float acc[2][4][4];
#pragma unroll
    for (int i = 0; i < 2; i++)
#pragma unroll
        for (int j = 0; j < 4; j++)
#pragma unroll
            for (int q = 0; q < 4; q++) acc[i][j][q] = 0.0f;

    gemm_mainloop_t<128, 512, 4>(acc, sb, &g_xs[0][0][0], &g_xs[1][0][0],
                                 &g_ws[0][0][0], &g_ws[1][0][0], m0, n0, t);

    const float invT = 1.0f / __ldg(temp);
    const int lr = lane >> 2;
    const int lc = (lane & 3) * 2;

#pragma unroll
    for (int mf = 0; mf < 2; mf++) {
        const int r0 = m0 + wm * 32 + mf * 16 + lr;
        const int r1 = r0 + 8;
        const int miss0 = g_anymiss[r0];
        const int miss1 = g_anymiss[r1];
        float* __restrict__ p0 = g_dec + (size_t)r0 * NODES_PAD;
        float* __restrict__ p1 = g_dec + (size_t)r1 * NODES_PAD;
#pragma unroll
        for (int nf = 0; nf < 4; nf++) {
            const int n = n0 + wn * 32 + nf * 8 + lc;
            const float bz0 = (n     < NODES) ? __ldg(&bias[n])     : 0.0f;
            const float bz1 = (n + 1 < NODES) ? __ldg(&bias[n + 1]) : 0.0f;
            const float* a4 = acc[mf][nf];
            float2 v0, v1;
            v0.x = miss0 ? 0.5f : 1.0f / (1.0f + __expf(-(a4[0] + bz0) * invT));
            v0.y = miss0 ? 0.5f : 1.0f / (1.0f + __expf(-(a4[1] + bz1) * invT));
            v1.x = miss1 ? 0.5f : 1.0f / (1.0f + __expf(-(a4[2] + bz0) * invT));
            v1.y = miss1 ? 0.5f : 1.0f / (1.0f + __expf(-(a4[3] + bz1) * invT));
            *(float2*)(p0 + n) = v0;
            *(float2*)(p1 + n) = v1;
        }
    }
}

// ---------------------------------------------------------------------------
// GEMM2: out = leaf_probs @ leaf_values (B = lv^T, n-major)
// ---------------------------------------------------------------------------
__global__ __launch_bounds__(256, 3)
void k_gemm2_mma(float* __restrict__ out)
{
    extern __shared__ char smem[];
    const uint32_t sb = smem_u32(smem);
    const int t    = threadIdx.x;
    const int warp = t >> 5;
    const int lane = t & 31;
    const int wm   = warp & 1;
    const int wn   = warp >> 1;
    const int m0   = blockIdx.x * 64;

    float acc[2][4][4];
#pragma unroll
    for (int i = 0; i < 2; i++)
#pragma unroll
        for (int j = 0; j < 4; j++)
#pragma unroll
            for (int q = 0; q < 4; q++) acc[i][j][q] = 0.0f;

    gemm_mainloop_t<64, 256, 2>(acc, sb, &g_ps[0][0][0], &g_ps[1][0][0],
                                &g_lvs[0][0][0], &g_lvs[1][0][0], m0, 0, t);

    const int lr = lane >> 2;
    const int lc = (lane & 3) * 2;
#pragma unroll
    for (int mf = 0; mf < 2; mf++) {
        const int r0 = m0 + wm * 32 + mf * 16 + lr;
        const int r1 = r0 + 8;
        float* __restrict__ p0 = out + (size_t)r0 * OUT_DIM;
        float* __restrict__ p1 = out + (size_t)r1 * OUT_DIM;
#pragma unroll
        for (int nf = 0; nf < 4; nf++) {
            const int n = wn * 32 + nf * 8 + lc;
            const float* a4 = acc[mf][nf];
            *(float2*)(p0 + n) = make_float2(a4[0], a4[1]);
            *(float2*)(p1 + n) = make_float2(a4[2], a4[3]);
        }
    }
}

// ---------------------------------------------------------------------------
// Routing kernel — CLOSED FORM, zero syncs.
// p(j) = prod_{L=0..9} [bit_L(j)==0 ? dec[2^L-1 + (j mod 2^L)] : 1-dec[...]]
// Thread tid owns leaves j = tid + 128*q (q=0..7): levels 0..7 fixed per
// thread (8 loads), level 8 has 2 candidates, level 9 has 4. No smem.
// Multiplication order L=0..9 matches the reference recurrence exactly.
// ---------------------------------------------------------------------------
__global__ __launch_bounds__(128) void k_route() {
    const int row = blockIdx.x;
    const int tid = threadIdx.x;           // 0..127
    const float* __restrict__ drow = g_dec + (size_t)row * NODES_PAD;

    // shared prefix: levels 0..6 (node = tid mod 2^L, sign = bit L of tid)
    float pre = 1.0f;
#pragma unroll
    for (int L = 0; L < 7; L++) {
        int node = (1 << L) - 1 + (tid & ((1 << L) - 1));
        float d = __ldg(&drow[node]);
        pre *= ((tid >> L) & 1) ? (1.0f - d) : d;
    }
    // level 7: node = 127 + tid (sign = q&1)
    const float d7 = __ldg(&drow[127 + tid]);
    // level 8: node = 255 + tid + 128*(q&1) (sign = (q>>1)&1)
    float d8[2];
#pragma unroll
    for (int i = 0; i < 2; i++) d8[i] = __ldg(&drow[255 + tid + 128 * i]);
    // level 9: node = 511 + tid + 128*(q&3) (sign = (q>>2)&1)
    float d9[4];
#pragma unroll
    for (int i = 0; i < 4; i++) d9[i] = __ldg(&drow[511 + tid + 128 * i]);

    __nv_bfloat16* __restrict__ ph = &g_ps[0][row][0];
    __nv_bfloat16* __restrict__ pl = &g_ps[1][row][0];
#pragma unroll
    for (int q = 0; q < 8; q++) {
        float p = pre;
        p *= (q & 1)        ? (1.0f - d7)        : d7;
        p *= ((q >> 1) & 1) ? (1.0f - d8[q & 1]) : d8[q & 1];
        p *= ((q >> 2) & 1) ? (1.0f - d9[q & 3]) : d9[q & 3];
        const int j = tid + 128 * q;
        __nv_bfloat16 h = __float2bfloat16(p);
        ph[j] = h;
        pl[j] = __float2bfloat16(p - __bfloat162float(h));
    }
}

// ---------------------------------------------------------------------------
// Launch
// ---------------------------------------------------------------------------
extern "C" void kernel_launch(void* const* d_in, const int* in_sizes, int n_in,
                              void* d_out, int out_size)
{
    const float* x    = (const float*)d_in[0];
    const float* w    = (const float*)d_in[1];
    const float* bias = (const float*)d_in[2];
    const float* lv   = (const float*)d_in[3];
    const float* temp = (const float*)d_in[4];
    float* out = (float*)d_out;

    static int smem_set = 0;
    if (!smem_set) {
        cudaFuncSetAttribute(k_gemm1_mma, cudaFuncAttributeMaxDynamicSharedMemorySize, G1_SMEM);
        cudaFuncSetAttribute(k_gemm2_mma, cudaFuncAttributeMaxDynamicSharedMemorySize, G2_SMEM);
        smem_set = 1;
    }

    k_convert_all<<<XB_BLOCKS + WB_BLOCKS + LV_BLOCKS, 256>>>(x, w, lv);
    {
        dim3 grid(NODES_PAD / 128, BATCH / 128);   // (8, 128)
        k_gemm1_mma<<<grid, 512, G1_SMEM>>>(bias, temp);
    }
    k_route<<<BATCH, 128>>>();
    k_gemm2_mma<<<BATCH / 64, 256, G2_SMEM>>>(out);
}